// round 1
// baseline (speedup 1.0000x reference)
#include <cuda_runtime.h>
#include <math.h>

// Problem constants
#define LN   2048
#define BN_  4
#define EN   1024
#define HN   8
#define D1N  2048
#define HDN  256
#define MN   (LN*BN_)   // 8192

// Scratch (device globals are the sanctioned scratch mechanism)
__device__ float g_x[MN * EN];    // normalized query (8192 x 1024)
__device__ float g_u[MN * D1N];   // silu(x @ u_w^T + u_b)
__device__ float g_v[MN * D1N];   // silu(x @ v_w^T + v_b)
__device__ float g_y[MN * D1N];   // toeplitz-mixed v
__device__ float g_t[HN * 2 * LN];// per-head toeplitz coeffs, index (i-j)+(L-1)

// ---------------------------------------------------------------------------
// Kernel 1: SimpleRMSNorm  x = q / (||q||/sqrt(E) + eps)
// ---------------------------------------------------------------------------
__global__ void rmsnorm_k(const float* __restrict__ q, float* __restrict__ x)
{
    int m = blockIdx.x;
    int t = threadIdx.x;                 // 256 threads, 4 floats each
    const float4* qr = reinterpret_cast<const float4*>(q + (size_t)m * EN);
    float4*       xr = reinterpret_cast<float4*>(x + (size_t)m * EN);
    float4 a = qr[t];
    float ss = a.x*a.x + a.y*a.y + a.z*a.z + a.w*a.w;
    #pragma unroll
    for (int o = 16; o; o >>= 1) ss += __shfl_xor_sync(0xffffffffu, ss, o);
    __shared__ float sred[8];
    if ((t & 31) == 0) sred[t >> 5] = ss;
    __syncthreads();
    if (t < 8) {
        float v = sred[t];
        #pragma unroll
        for (int o = 4; o; o >>= 1) v += __shfl_xor_sync(0xffu, v, o);
        if (t == 0) sred[0] = v;
    }
    __syncthreads();
    float inv = 1.0f / (sqrtf(sred[0] * (1.0f / EN)) + 1e-8f);
    a.x *= inv; a.y *= inv; a.z *= inv; a.w *= inv;
    xr[t] = a;
}

// ---------------------------------------------------------------------------
// Kernel 2: build toeplitz coefficient strip per head.
//   g_t[h][ (i-j)+(L-1) ] = t_{i-j};  t_0=zero[h], t_k=pos[h][k-1], t_{-k}=neg[h][k-1]
// ---------------------------------------------------------------------------
__global__ void build_t_k(const float* __restrict__ pos, const float* __restrict__ zero,
                          const float* __restrict__ neg)
{
    int h = blockIdx.y;
    int k = blockIdx.x * blockDim.x + threadIdx.x;
    if (k >= LN) return;
    float* tt = g_t + h * 2 * LN;
    if (k == 0) {
        tt[LN - 1] = zero[h];
    } else {
        tt[LN - 1 + k] = pos[h * (LN - 1) + k - 1];
        tt[LN - 1 - k] = neg[h * (LN - 1) + k - 1];
    }
}

// ---------------------------------------------------------------------------
// Kernel 3: NT GEMM + bias + silu:  C[m][n] = silu( sum_k A[m][k]*W[n][k] + bias[n] )
// A: MxK row-major, W: NxK row-major. Tile 128x128x16, 256 thr, 8x8/thread.
// ---------------------------------------------------------------------------
__global__ void __launch_bounds__(256, 2)
gemm_nt_silu_k(const float* __restrict__ A, const float* __restrict__ W,
               const float* __restrict__ bias, float* __restrict__ C,
               int K, int ldc)
{
    __shared__ __align__(16) float As[16][132];
    __shared__ __align__(16) float Bs[16][132];
    int tid = threadIdx.x;
    int tx = tid & 15, ty = tid >> 4;
    int i0 = blockIdx.y * 128;
    int n0 = blockIdx.x * 128;
    int lr = tid >> 2;            // 0..63
    int lc = (tid & 3) * 4;       // 0,4,8,12
    float acc[8][8] = {};
    for (int kt = 0; kt < K; kt += 16) {
        #pragma unroll
        for (int p = 0; p < 2; p++) {
            int r = lr + p * 64;
            float4 av = *reinterpret_cast<const float4*>(&A[(size_t)(i0 + r) * K + kt + lc]);
            As[lc+0][r] = av.x; As[lc+1][r] = av.y; As[lc+2][r] = av.z; As[lc+3][r] = av.w;
            float4 wv = *reinterpret_cast<const float4*>(&W[(size_t)(n0 + r) * K + kt + lc]);
            Bs[lc+0][r] = wv.x; Bs[lc+1][r] = wv.y; Bs[lc+2][r] = wv.z; Bs[lc+3][r] = wv.w;
        }
        __syncthreads();
        #pragma unroll
        for (int kk = 0; kk < 16; kk++) {
            float4 a0 = *reinterpret_cast<float4*>(&As[kk][ty*8]);
            float4 a1 = *reinterpret_cast<float4*>(&As[kk][ty*8+4]);
            float4 b0 = *reinterpret_cast<float4*>(&Bs[kk][tx*8]);
            float4 b1 = *reinterpret_cast<float4*>(&Bs[kk][tx*8+4]);
            float ra[8] = {a0.x,a0.y,a0.z,a0.w,a1.x,a1.y,a1.z,a1.w};
            float rb[8] = {b0.x,b0.y,b0.z,b0.w,b1.x,b1.y,b1.z,b1.w};
            #pragma unroll
            for (int i = 0; i < 8; i++)
                #pragma unroll
                for (int j = 0; j < 8; j++)
                    acc[i][j] += ra[i] * rb[j];
        }
        __syncthreads();
    }
    #pragma unroll
    for (int i = 0; i < 8; i++) {
        int m = i0 + ty * 8 + i;
        #pragma unroll
        for (int j = 0; j < 8; j++) {
            int n = n0 + tx * 8 + j;
            float s = acc[i][j] + bias[n];
            C[(size_t)m * ldc + n] = s / (1.0f + __expf(-s));
        }
    }
}

// ---------------------------------------------------------------------------
// Kernel 4: Toeplitz mix as GEMM per head.
//   Y_h(i, col) = sum_j tt[h][(i-j)+(L-1)] * V_h(j, col),  col=(b,d), b=n0/256
// A-operand tile is generated from a 143-float coefficient strip (shared mem).
// ---------------------------------------------------------------------------
__global__ void __launch_bounds__(256, 2)
toeplitz_k(const float* __restrict__ V, float* __restrict__ Y)
{
    __shared__ __align__(16) float Bs[16][132];
    __shared__ float strip[160];
    int tid = threadIdx.x;
    int tx = tid & 15, ty = tid >> 4;
    int h  = blockIdx.z;
    int i0 = blockIdx.y * 128;        // L rows
    int n0 = blockIdx.x * 128;        // col within B*hd = 1024
    int b  = n0 / HDN;                // constant within the tile (HDN=256, BN=128)
    int d0 = n0 % HDN;
    const float* tt = g_t + h * 2 * LN;
    const float* vb = V + (size_t)b * D1N + h * HDN + d0;   // + j*(BN_*D1N) + col
    int brow = tid >> 5;              // 0..7
    int bcol = (tid & 31) * 4;        // 0..124
    float acc[8][8] = {};
    for (int k0 = 0; k0 < LN; k0 += 16) {
        if (tid < 143) strip[tid] = tt[(LN - 1) + i0 - k0 - 15 + tid];
        #pragma unroll
        for (int p = 0; p < 2; p++) {
            int kk = brow + p * 8;
            float4 bv = *reinterpret_cast<const float4*>(&vb[(size_t)(k0 + kk) * (BN_ * D1N) + bcol]);
            *reinterpret_cast<float4*>(&Bs[kk][bcol]) = bv;
        }
        __syncthreads();
        // Per-thread coefficient window: strip[ty*8 .. ty*8+22], all static indices after unroll
        float sreg[23];
        #pragma unroll
        for (int s = 0; s < 23; s++) sreg[s] = strip[ty * 8 + s];
        #pragma unroll
        for (int kk = 0; kk < 16; kk++) {
            float4 b0 = *reinterpret_cast<float4*>(&Bs[kk][tx*8]);
            float4 b1 = *reinterpret_cast<float4*>(&Bs[kk][tx*8+4]);
            float rb[8] = {b0.x,b0.y,b0.z,b0.w,b1.x,b1.y,b1.z,b1.w};
            #pragma unroll
            for (int i = 0; i < 8; i++) {
                float ra = sreg[i + 15 - kk];   // = T[i0+ty*8+i][k0+kk]
                #pragma unroll
                for (int j = 0; j < 8; j++) acc[i][j] += ra * rb[j];
            }
        }
        __syncthreads();
    }
    #pragma unroll
    for (int i = 0; i < 8; i++) {
        int ii = i0 + ty * 8 + i;
        float* yr = Y + ((size_t)ii * BN_ + b) * D1N + h * HDN + d0;
        #pragma unroll
        for (int j = 0; j < 8; j++) yr[tx * 8 + j] = acc[i][j];
    }
}

// ---------------------------------------------------------------------------
// Kernel 5: final GEMM with fused gating, bias and residual:
//   out[m][e] = sum_f (U[m][f]*Y[m][f]) * o_w[e][f] + o_b[e] + q[m][e]
// ---------------------------------------------------------------------------
__global__ void __launch_bounds__(256, 2)
gemm_final_k(const float* __restrict__ U, const float* __restrict__ Yv,
             const float* __restrict__ W, const float* __restrict__ bias,
             const float* __restrict__ q, float* __restrict__ C)
{
    const int K = D1N;
    __shared__ __align__(16) float As[16][132];
    __shared__ __align__(16) float Bs[16][132];
    int tid = threadIdx.x;
    int tx = tid & 15, ty = tid >> 4;
    int i0 = blockIdx.y * 128;
    int n0 = blockIdx.x * 128;
    int lr = tid >> 2;
    int lc = (tid & 3) * 4;
    float acc[8][8] = {};
    for (int kt = 0; kt < K; kt += 16) {
        #pragma unroll
        for (int p = 0; p < 2; p++) {
            int r = lr + p * 64;
            size_t aoff = (size_t)(i0 + r) * K + kt + lc;
            float4 uv = *reinterpret_cast<const float4*>(&U[aoff]);
            float4 yv = *reinterpret_cast<const float4*>(&Yv[aoff]);
            As[lc+0][r] = uv.x * yv.x; As[lc+1][r] = uv.y * yv.y;
            As[lc+2][r] = uv.z * yv.z; As[lc+3][r] = uv.w * yv.w;
            float4 wv = *reinterpret_cast<const float4*>(&W[(size_t)(n0 + r) * K + kt + lc]);
            Bs[lc+0][r] = wv.x; Bs[lc+1][r] = wv.y; Bs[lc+2][r] = wv.z; Bs[lc+3][r] = wv.w;
        }
        __syncthreads();
        #pragma unroll
        for (int kk = 0; kk < 16; kk++) {
            float4 a0 = *reinterpret_cast<float4*>(&As[kk][ty*8]);
            float4 a1 = *reinterpret_cast<float4*>(&As[kk][ty*8+4]);
            float4 b0 = *reinterpret_cast<float4*>(&Bs[kk][tx*8]);
            float4 b1 = *reinterpret_cast<float4*>(&Bs[kk][tx*8+4]);
            float ra[8] = {a0.x,a0.y,a0.z,a0.w,a1.x,a1.y,a1.z,a1.w};
            float rb[8] = {b0.x,b0.y,b0.z,b0.w,b1.x,b1.y,b1.z,b1.w};
            #pragma unroll
            for (int i = 0; i < 8; i++)
                #pragma unroll
                for (int j = 0; j < 8; j++)
                    acc[i][j] += ra[i] * rb[j];
        }
        __syncthreads();
    }
    #pragma unroll
    for (int i = 0; i < 8; i++) {
        int m = i0 + ty * 8 + i;
        #pragma unroll
        for (int j = 0; j < 8; j++) {
            int n = n0 + tx * 8 + j;
            C[(size_t)m * EN + n] = acc[i][j] + bias[n] + q[(size_t)m * EN + n];
        }
    }
}

// ---------------------------------------------------------------------------
extern "C" void kernel_launch(void* const* d_in, const int* in_sizes, int n_in,
                              void* d_out, int out_size)
{
    const float* q   = (const float*)d_in[0];
    // d_in[1] = key, d_in[2] = value : unused by the reference
    const float* u_w = (const float*)d_in[3];
    const float* u_b = (const float*)d_in[4];
    const float* v_w = (const float*)d_in[5];
    const float* v_b = (const float*)d_in[6];
    const float* o_w = (const float*)d_in[7];
    const float* o_b = (const float*)d_in[8];
    const float* pos = (const float*)d_in[9];
    const float* zer = (const float*)d_in[10];
    const float* neg = (const float*)d_in[11];
    float* out = (float*)d_out;

    void *px, *pu, *pv, *py;
    cudaGetSymbolAddress(&px, g_x);
    cudaGetSymbolAddress(&pu, g_u);
    cudaGetSymbolAddress(&pv, g_v);
    cudaGetSymbolAddress(&py, g_y);
    float* xg = (float*)px;
    float* ug = (float*)pu;
    float* vg = (float*)pv;
    float* yg = (float*)py;

    // 1. RMSNorm
    rmsnorm_k<<<MN, 256>>>(q, xg);
    // 2. Toeplitz coefficient strips
    build_t_k<<<dim3(LN / 256, HN), 256>>>(pos, zer, neg);
    // 3. u = silu(x @ u_w^T + u_b)
    gemm_nt_silu_k<<<dim3(D1N / 128, MN / 128), 256>>>(xg, u_w, u_b, ug, EN, D1N);
    // 4. v = silu(x @ v_w^T + v_b)
    gemm_nt_silu_k<<<dim3(D1N / 128, MN / 128), 256>>>(xg, v_w, v_b, vg, EN, D1N);
    // 5. y = toeplitz_mix(v)
    toeplitz_k<<<dim3((BN_ * HDN) / 128, LN / 128, HN), 256>>>(vg, yg);
    // 6. out = (u * y) @ o_w^T + o_b + q
    gemm_final_k<<<dim3(EN / 128, MN / 128), 256>>>(ug, yg, o_w, o_b, q, out);
}

// round 3
// speedup vs baseline: 1.9537x; 1.9537x over previous
#include <cuda_runtime.h>
#include <cuda_bf16.h>
#include <cstdint>
#include <math.h>

#define LN   2048
#define BN_  4
#define EN   1024
#define HN   8
#define D1N  2048
#define HDN  256
#define MN   (LN*BN_)   // 8192

// tcgen05 only on arch-specific ("a") targets; plain sm_103 gets mma.sync.
#if defined(__CUDA_ARCH__) && (defined(__CUDA_ARCH_FEAT_SM103_ALL) || defined(__CUDA_ARCH_FEAT_SM100_ALL))
#define TC_PATH 1
#else
#define TC_PATH 0
#endif

// ---------------- device scratch ----------------
__device__ __align__(16) __nv_bfloat16 g_xh[MN*EN],  g_xl[MN*EN];
__device__ __align__(16) __nv_bfloat16 g_uwh[D1N*EN], g_uwl[D1N*EN];
__device__ __align__(16) __nv_bfloat16 g_vwh[D1N*EN], g_vwl[D1N*EN];
__device__ __align__(16) __nv_bfloat16 g_owh[EN*D1N], g_owl[EN*D1N];
__device__ __align__(16) float g_u[MN*D1N];
__device__ __align__(16) float g_v[MN*D1N];
__device__ __align__(16) __nv_bfloat16 g_vth[(size_t)32*HDN*LN], g_vtl[(size_t)32*HDN*LN];
__device__ __align__(16) __nv_bfloat16 g_ah[MN*D1N], g_al[MN*D1N];
__device__ __align__(16) __nv_bfloat16 g_th[HN*4096], g_tl[HN*4096];

// ---------------- helpers ----------------
__device__ __forceinline__ uint32_t smem_u32(const void* p){
    uint32_t a;
    asm("{ .reg .u64 t; cvta.to.shared.u64 t, %1; cvt.u32.u64 %0, t; }" : "=r"(a) : "l"(p));
    return a;
}
#define SWZ(o) ((uint32_t)(o) ^ ((((uint32_t)(o))>>3)&0x70))

__device__ __forceinline__ uint32_t pk(float a, float b){
    __nv_bfloat16 x = __float2bfloat16(a), y = __float2bfloat16(b);
    return (uint32_t)__bfloat16_as_ushort(x) | ((uint32_t)__bfloat16_as_ushort(y)<<16);
}

#if TC_PATH
__device__ __forceinline__ uint32_t elect1(){
    uint32_t r;
    asm volatile("{ .reg .pred p; elect.sync _|p, 0xFFFFFFFF; selp.b32 %0,1,0,p; }" : "=r"(r));
    return r;
}
static constexpr unsigned long long DESC_BASE =
    (2ull<<61) | (1ull<<46) | (64ull<<32) | (1ull<<16);   // SW128, Blackwell, SBO=64, LBO=1
__device__ __forceinline__ uint64_t mkdesc(uint32_t a){ return DESC_BASE | ((uint64_t)((a>>4)&0x3FFF)); }
// idesc: dtype=F32, atype=btype=BF16, N=128, M=128
static constexpr uint32_t IDESC = (1u<<4)|(1u<<7)|(1u<<10)|((128u/8u)<<17)|((128u/16u)<<24);

__device__ __forceinline__ void mma_ss(uint32_t d, uint64_t da, uint64_t db, int en){
    asm volatile(
        "{\n\t.reg .pred p;\n\tsetp.ne.s32 p, %4, 0;\n\t"
        "tcgen05.mma.cta_group::1.kind::f16 [%0], %1, %2, %3, {%5,%5,%5,%5}, p;\n\t}"
        :: "r"(d), "l"(da), "l"(db), "r"(IDESC), "r"(en), "r"(0u) : "memory");
}
__device__ __forceinline__ void mbar_wait(uint32_t mb, uint32_t par){
    asm volatile(
        "{\n\t.reg .pred P1;\n\t"
        "WL_%=:\n\t"
        "mbarrier.try_wait.parity.acquire.cta.shared::cta.b64 P1, [%0], %1, 0x989680;\n\t"
        "@P1 bra.uni WD_%=;\n\t"
        "bra.uni WL_%=;\n\t"
        "WD_%=:\n\t}"
        :: "r"(mb), "r"(par) : "memory");
}
__device__ __forceinline__ void tmem_ld32(uint32_t* r, uint32_t addr){
    asm volatile(
        "tcgen05.ld.sync.aligned.32x32b.x32.b32 "
        "{%0, %1, %2, %3, %4, %5, %6, %7, %8, %9, %10, %11, %12, %13, %14, %15, "
        " %16, %17, %18, %19, %20, %21, %22, %23, %24, %25, %26, %27, %28, %29, %30, %31}, [%32];"
        : "=r"(r[0]), "=r"(r[1]), "=r"(r[2]), "=r"(r[3]), "=r"(r[4]), "=r"(r[5]), "=r"(r[6]), "=r"(r[7]),
          "=r"(r[8]), "=r"(r[9]), "=r"(r[10]),"=r"(r[11]),"=r"(r[12]),"=r"(r[13]),"=r"(r[14]),"=r"(r[15]),
          "=r"(r[16]),"=r"(r[17]),"=r"(r[18]),"=r"(r[19]),"=r"(r[20]),"=r"(r[21]),"=r"(r[22]),"=r"(r[23]),
          "=r"(r[24]),"=r"(r[25]),"=r"(r[26]),"=r"(r[27]),"=r"(r[28]),"=r"(r[29]),"=r"(r[30]),"=r"(r[31])
        : "r"(addr));
}
#else
__device__ __forceinline__ void ldsm4(uint32_t* r, uint32_t addr){
    asm volatile("ldmatrix.sync.aligned.m8n8.x4.shared.b16 {%0,%1,%2,%3}, [%4];"
                 : "=r"(r[0]),"=r"(r[1]),"=r"(r[2]),"=r"(r[3]) : "r"(addr));
}
__device__ __forceinline__ void ldsm2(uint32_t* r, uint32_t addr){
    asm volatile("ldmatrix.sync.aligned.m8n8.x2.shared.b16 {%0,%1}, [%2];"
                 : "=r"(r[0]),"=r"(r[1]) : "r"(addr));
}
__device__ __forceinline__ void mma16816(float* d, const uint32_t* a, const uint32_t* b){
    asm volatile("mma.sync.aligned.m16n8k16.row.col.f32.bf16.bf16.f32 "
        "{%0,%1,%2,%3}, {%4,%5,%6,%7}, {%8,%9}, {%0,%1,%2,%3};"
        : "+f"(d[0]),"+f"(d[1]),"+f"(d[2]),"+f"(d[3])
        : "r"(a[0]),"r"(a[1]),"r"(a[2]),"r"(a[3]), "r"(b[0]),"r"(b[1]));
}
#endif

// SMEM layout: [0] tmem ptr, [8] mbar, [16..816) toeplitz strip staging,
// tiles at 1024: A_hi 16KB, A_lo 16KB, B_hi 16KB, B_lo 16KB (128 rows x 64 bf16)
#define OA_H 1024
#define OA_L (OA_H+16384)
#define OB_H (OA_L+16384)
#define OB_L (OB_H+16384)
#define SMEM_SZ (OB_L+16384)   // 66560

// ---------------------------------------------------------------------------
__global__ void rmsnorm_k(const float* __restrict__ q,
                          __nv_bfloat16* __restrict__ xh, __nv_bfloat16* __restrict__ xl)
{
    int m = blockIdx.x, t = threadIdx.x;
    float4 a = reinterpret_cast<const float4*>(q + (size_t)m*EN)[t];
    float ss = a.x*a.x + a.y*a.y + a.z*a.z + a.w*a.w;
    #pragma unroll
    for (int o=16;o;o>>=1) ss += __shfl_xor_sync(0xffffffffu, ss, o);
    __shared__ float sred[8];
    if ((t&31)==0) sred[t>>5] = ss;
    __syncthreads();
    if (t<8){
        float v = sred[t];
        #pragma unroll
        for (int o=4;o;o>>=1) v += __shfl_xor_sync(0xffu, v, o);
        if (t==0) sred[0] = v;
    }
    __syncthreads();
    float inv = 1.0f / (sqrtf(sred[0]*(1.0f/EN)) + 1e-8f);
    float v0=a.x*inv, v1=a.y*inv, v2=a.z*inv, v3=a.w*inv;
    __nv_bfloat16 h0=__float2bfloat16(v0), h1=__float2bfloat16(v1),
                  h2=__float2bfloat16(v2), h3=__float2bfloat16(v3);
    size_t off = (size_t)m*EN + t*4;
    uint2 wh = make_uint2(
        (uint32_t)__bfloat16_as_ushort(h0) | ((uint32_t)__bfloat16_as_ushort(h1)<<16),
        (uint32_t)__bfloat16_as_ushort(h2) | ((uint32_t)__bfloat16_as_ushort(h3)<<16));
    uint2 wl = make_uint2(
        pk(v0-__bfloat162float(h0), v1-__bfloat162float(h1)),
        pk(v2-__bfloat162float(h2), v3-__bfloat162float(h3)));
    *reinterpret_cast<uint2*>(xh+off) = wh;
    *reinterpret_cast<uint2*>(xl+off) = wl;
}

__global__ void split_k(const float* __restrict__ w,
                        __nv_bfloat16* __restrict__ oh, __nv_bfloat16* __restrict__ ol, int n4)
{
    int i = blockIdx.x*256 + threadIdx.x;
    if (i >= n4) return;
    float4 a = reinterpret_cast<const float4*>(w)[i];
    __nv_bfloat16 h0=__float2bfloat16(a.x), h1=__float2bfloat16(a.y),
                  h2=__float2bfloat16(a.z), h3=__float2bfloat16(a.w);
    uint2 wh = make_uint2(
        (uint32_t)__bfloat16_as_ushort(h0) | ((uint32_t)__bfloat16_as_ushort(h1)<<16),
        (uint32_t)__bfloat16_as_ushort(h2) | ((uint32_t)__bfloat16_as_ushort(h3)<<16));
    uint2 wl = make_uint2(
        pk(a.x-__bfloat162float(h0), a.y-__bfloat162float(h1)),
        pk(a.z-__bfloat162float(h2), a.w-__bfloat162float(h3)));
    reinterpret_cast<uint2*>(oh)[i] = wh;
    reinterpret_cast<uint2*>(ol)[i] = wl;
}

__global__ void build_t_k(const float* __restrict__ pos, const float* __restrict__ zero,
                          const float* __restrict__ neg)
{
    int h = blockIdx.y;
    int k = blockIdx.x*256 + threadIdx.x;
    if (k >= LN) return;
    int base = h*4096;
    auto wr = [&](int idx, float v){
        __nv_bfloat16 hi = __float2bfloat16(v);
        g_th[base+idx] = hi;
        g_tl[base+idx] = __float2bfloat16(v - __bfloat162float(hi));
    };
    if (k==0){ wr(2047, zero[h]); wr(4095, 0.f); }
    else { wr(2047+k, pos[h*(LN-1)+k-1]); wr(2047-k, neg[h*(LN-1)+k-1]); }
}

// ---------------------------------------------------------------------------
// split-bf16 GEMM, tile 128x128, K-chunk 64.
// C = Ah*Bh^T + Ah*Bl^T + Al*Bh^T (+epilogue). EPI 0: silu(acc+bias). EPI 1: +bias+resid.
// ---------------------------------------------------------------------------
template<int EPI>
__global__ void __launch_bounds__(256) __cluster_dims__(1,1,1)
gemm_k(const __nv_bfloat16* __restrict__ Ah, const __nv_bfloat16* __restrict__ Al,
       const __nv_bfloat16* __restrict__ Bh, const __nv_bfloat16* __restrict__ Bl,
       const float* __restrict__ bias, const float* __restrict__ resid,
       float* __restrict__ C, int K, int Nld)
{
    extern __shared__ char smem[];
    const uint32_t sb = smem_u32(smem);
    int tid = threadIdx.x, wid = tid>>5, lid = tid&31;
    int i0 = blockIdx.y*128, n0 = blockIdx.x*128;

#if TC_PATH
    if (wid==0)
        asm volatile("tcgen05.alloc.cta_group::1.sync.aligned.shared::cta.b32 [%0], %1;"
                     :: "r"(sb), "r"(128u) : "memory");
    if (tid==0)
        asm volatile("mbarrier.init.shared.b64 [%0], %1;" :: "r"(sb+8), "r"(1u) : "memory");
    __syncthreads();
    uint32_t tb;
    asm volatile("ld.shared.b32 %0, [%1];" : "=r"(tb) : "r"(sb));
#else
    int wm0 = (wid>>2)*64, wn0 = (wid&3)*32;
    float acc[4][4][4];
    #pragma unroll
    for (int i=0;i<4;i++)
        #pragma unroll
        for (int j=0;j<4;j++)
            #pragma unroll
            for (int r=0;r<4;r++) acc[i][j][r] = 0.f;
#endif

    const int nch = K>>6;
    for (int c=0;c<nch;c++){
#if TC_PATH
        if (c>0) mbar_wait(sb+8, (c-1)&1);
#else
        if (c>0) __syncthreads();
#endif
        const int kt = c<<6;
        #pragma unroll
        for (int it=0;it<4;it++){
            int idx = it*256+tid, r = idx>>3, qq = idx&7;
            size_t goA = (size_t)(i0+r)*K + kt + qq*8;
            size_t goB = (size_t)(n0+r)*K + kt + qq*8;
            uint32_t so = SWZ(r*128 + qq*16);
            *(uint4*)(smem+OA_H+so) = *(const uint4*)(Ah+goA);
            *(uint4*)(smem+OA_L+so) = *(const uint4*)(Al+goA);
            *(uint4*)(smem+OB_H+so) = *(const uint4*)(Bh+goB);
            *(uint4*)(smem+OB_L+so) = *(const uint4*)(Bl+goB);
        }
#if TC_PATH
        asm volatile("fence.proxy.async.shared::cta;" ::: "memory");
        __syncthreads();
        if (wid==0 && elect1()){
            uint64_t dah = mkdesc(sb+OA_H), dal = mkdesc(sb+OA_L);
            uint64_t dbh = mkdesc(sb+OB_H), dbl = mkdesc(sb+OB_L);
            uint64_t da[3] = {dah, dah, dal};
            uint64_t db[3] = {dbh, dbl, dbh};
            #pragma unroll
            for (int sg=0;sg<3;sg++)
                #pragma unroll
                for (int k=0;k<4;k++)
                    mma_ss(tb, da[sg]+k*2, db[sg]+k*2, (c|sg|k)!=0);
            asm volatile("tcgen05.commit.cta_group::1.mbarrier::arrive::one.shared::cluster.b64 [%0];"
                         :: "r"(sb+8) : "memory");
        }
#else
        __syncthreads();
        #pragma unroll
        for (int ks=0;ks<4;ks++){
            uint32_t ahf[4][4], alf[4][4], bhf[4][2], blf[4][2];
            int arow = ((lid>>3)&1)*8 + (lid&7);
            int acol = ks*16 + ((lid>>4)&1)*8;
            #pragma unroll
            for (int mi=0;mi<4;mi++){
                uint32_t off = SWZ((wm0+mi*16+arow)*128 + acol*2);
                ldsm4(ahf[mi], sb+OA_H+off);
                ldsm4(alf[mi], sb+OA_L+off);
            }
            int l2 = lid&15;
            int brow = l2&7;
            int bcol = ks*16 + ((l2>>3)&1)*8;
            #pragma unroll
            for (int ni=0;ni<4;ni++){
                uint32_t off = SWZ((wn0+ni*8+brow)*128 + bcol*2);
                ldsm2(bhf[ni], sb+OB_H+off);
                ldsm2(blf[ni], sb+OB_L+off);
            }
            #pragma unroll
            for (int mi=0;mi<4;mi++)
                #pragma unroll
                for (int ni=0;ni<4;ni++){
                    mma16816(acc[mi][ni], ahf[mi], bhf[ni]);
                    mma16816(acc[mi][ni], ahf[mi], blf[ni]);
                    mma16816(acc[mi][ni], alf[mi], bhf[ni]);
                }
        }
#endif
    }

#if TC_PATH
    mbar_wait(sb+8, (nch-1)&1);
    asm volatile("tcgen05.fence::after_thread_sync;" ::: "memory");
    if (wid<4){
        int m = i0 + wid*32 + lid;
        #pragma unroll
        for (int nb=0;nb<4;nb++){
            uint32_t dr[32];
            tmem_ld32(dr, tb + nb*32);
            asm volatile("tcgen05.wait::ld.sync.aligned;" ::: "memory");
            float o[32];
            const float* bp = bias + n0 + nb*32;
            const float* rp = (EPI==1) ? (resid + (size_t)m*Nld + n0 + nb*32) : nullptr;
            #pragma unroll
            for (int j=0;j<32;j++){
                float v = __uint_as_float(dr[j]);
                if (EPI==0){ float s = v + bp[j]; o[j] = s / (1.0f + __expf(-s)); }
                else       { o[j] = v + bp[j] + rp[j]; }
            }
            float4* dst = (float4*)(C + (size_t)m*Nld + n0 + nb*32);
            #pragma unroll
            for (int w=0;w<8;w++) dst[w] = make_float4(o[4*w],o[4*w+1],o[4*w+2],o[4*w+3]);
        }
    }
    __syncthreads();
    if (wid==0){
        asm volatile("tcgen05.relinquish_alloc_permit.cta_group::1.sync.aligned;");
        asm volatile("tcgen05.dealloc.cta_group::1.sync.aligned.b32 %0, %1;" :: "r"(tb), "r"(128u));
    }
#else
    #pragma unroll
    for (int mi=0;mi<4;mi++)
        #pragma unroll
        for (int ni=0;ni<4;ni++){
            int nn = n0 + wn0 + ni*8 + 2*(lid&3);
            #pragma unroll
            for (int half=0;half<2;half++){
                int m = i0 + wm0 + mi*16 + (lid>>2) + half*8;
                float v0 = acc[mi][ni][2*half+0], v1 = acc[mi][ni][2*half+1];
                float o0, o1;
                if (EPI==0){
                    float s0 = v0 + bias[nn], s1 = v1 + bias[nn+1];
                    o0 = s0 / (1.0f + __expf(-s0)); o1 = s1 / (1.0f + __expf(-s1));
                } else {
                    const float* rp = resid + (size_t)m*Nld + nn;
                    o0 = v0 + bias[nn] + rp[0]; o1 = v1 + bias[nn+1] + rp[1];
                }
                *(float2*)(C + (size_t)m*Nld + nn) = make_float2(o0, o1);
            }
        }
#endif
}

// ---------------------------------------------------------------------------
// transpose + split v
// ---------------------------------------------------------------------------
__global__ void transsplit_k(const float* __restrict__ V,
                             __nv_bfloat16* __restrict__ Oh, __nv_bfloat16* __restrict__ Ol)
{
    __shared__ float t[32][33];
    int s = blockIdx.z, h = s>>2, b = s&3;
    int j0 = blockIdx.x*32, d0 = blockIdx.y*32;
    int tx = threadIdx.x, ty = threadIdx.y;
    #pragma unroll
    for (int r=0;r<4;r++){
        int j = j0 + ty + r*8;
        t[ty+r*8][tx] = V[((size_t)j*BN_ + b)*D1N + h*HDN + d0 + tx];
    }
    __syncthreads();
    #pragma unroll
    for (int r=0;r<4;r++){
        int d = d0 + ty + r*8;
        float v = t[tx][ty+r*8];
        __nv_bfloat16 hi = __float2bfloat16(v);
        size_t off = ((size_t)s*HDN + d)*LN + j0 + tx;
        Oh[off] = hi;
        Ol[off] = __float2bfloat16(v - __bfloat162float(hi));
    }
}

// ---------------------------------------------------------------------------
// Toeplitz mix as GEMM with generated A tiles + fused gating epilogue.
// Tile: 128 (L rows) x 128 (d cols of 256), K-chunk 64 over j.
// ---------------------------------------------------------------------------
__global__ void __launch_bounds__(256) __cluster_dims__(1,1,1)
toep_k(const __nv_bfloat16* __restrict__ Vh_, const __nv_bfloat16* __restrict__ Vl_,
       const __nv_bfloat16* __restrict__ Th_, const __nv_bfloat16* __restrict__ Tl_,
       const float* __restrict__ U,
       __nv_bfloat16* __restrict__ Aoh, __nv_bfloat16* __restrict__ Aol)
{
    extern __shared__ char smem[];
    const uint32_t sb = smem_u32(smem);
    uint16_t* sH = (uint16_t*)(smem+16);
    uint16_t* sL = (uint16_t*)(smem+432);
    int tid = threadIdx.x, wid = tid>>5, lid = tid&31;
    int s = blockIdx.z, h = s>>2, b = s&3;
    int i0 = blockIdx.y*128;
    int d0 = blockIdx.x*128;
    const __nv_bfloat16* vh = Vh_ + (size_t)s*HDN*LN + (size_t)d0*LN;
    const __nv_bfloat16* vl = Vl_ + (size_t)s*HDN*LN + (size_t)d0*LN;
    const uint16_t* th = (const uint16_t*)(Th_ + h*4096);
    const uint16_t* tl = (const uint16_t*)(Tl_ + h*4096);

#if TC_PATH
    if (wid==0)
        asm volatile("tcgen05.alloc.cta_group::1.sync.aligned.shared::cta.b32 [%0], %1;"
                     :: "r"(sb), "r"(128u) : "memory");
    if (tid==0)
        asm volatile("mbarrier.init.shared.b64 [%0], %1;" :: "r"(sb+8), "r"(1u) : "memory");
    __syncthreads();
    uint32_t tb;
    asm volatile("ld.shared.b32 %0, [%1];" : "=r"(tb) : "r"(sb));
#else
    int wm0 = (wid>>2)*64, wn0 = (wid&3)*32;
    float acc[4][4][4];
    #pragma unroll
    for (int i=0;i<4;i++)
        #pragma unroll
        for (int j=0;j<4;j++)
            #pragma unroll
            for (int r=0;r<4;r++) acc[i][j][r] = 0.f;
#endif

    for (int c=0;c<32;c++){
#if TC_PATH
        if (c>0) mbar_wait(sb+8, (c-1)&1);
#else
        if (c>0) __syncthreads();
#endif
        int j0 = c<<6;
        int gbase = 1984 + i0 - j0;
        if (tid < 191){ sH[tid] = th[gbase+tid]; sL[tid] = tl[gbase+tid]; }
        #pragma unroll
        for (int it=0;it<4;it++){
            int idx = it*256+tid, r = idx>>3, qq = idx&7;
            size_t go = (size_t)r*LN + j0 + qq*8;
            uint32_t so = SWZ(r*128 + qq*16);
            *(uint4*)(smem+OB_H+so) = *(const uint4*)(vh+go);
            *(uint4*)(smem+OB_L+so) = *(const uint4*)(vl+go);
        }
        __syncthreads();   // strip + B staged
        #pragma unroll
        for (int it=0;it<4;it++){
            int idx = it*256+tid, m = idx>>3, k8 = (idx&7)<<3;
            int base = m + 63 - k8;
            uint32_t so = SWZ(m*128 + k8*2);
            uint32_t w0 = (uint32_t)sH[base]   | ((uint32_t)sH[base-1]<<16);
            uint32_t w1 = (uint32_t)sH[base-2] | ((uint32_t)sH[base-3]<<16);
            uint32_t w2 = (uint32_t)sH[base-4] | ((uint32_t)sH[base-5]<<16);
            uint32_t w3 = (uint32_t)sH[base-6] | ((uint32_t)sH[base-7]<<16);
            *(uint4*)(smem+OA_H+so) = make_uint4(w0,w1,w2,w3);
            w0 = (uint32_t)sL[base]   | ((uint32_t)sL[base-1]<<16);
            w1 = (uint32_t)sL[base-2] | ((uint32_t)sL[base-3]<<16);
            w2 = (uint32_t)sL[base-4] | ((uint32_t)sL[base-5]<<16);
            w3 = (uint32_t)sL[base-6] | ((uint32_t)sL[base-7]<<16);
            *(uint4*)(smem+OA_L+so) = make_uint4(w0,w1,w2,w3);
        }
#if TC_PATH
        asm volatile("fence.proxy.async.shared::cta;" ::: "memory");
        __syncthreads();
        if (wid==0 && elect1()){
            uint64_t dah = mkdesc(sb+OA_H), dal = mkdesc(sb+OA_L);
            uint64_t dbh = mkdesc(sb+OB_H), dbl = mkdesc(sb+OB_L);
            uint64_t da[3] = {dah, dah, dal};
            uint64_t db[3] = {dbh, dbl, dbh};
            #pragma unroll
            for (int sg=0;sg<3;sg++)
                #pragma unroll
                for (int k=0;k<4;k++)
                    mma_ss(tb, da[sg]+k*2, db[sg]+k*2, (c|sg|k)!=0);
            asm volatile("tcgen05.commit.cta_group::1.mbarrier::arrive::one.shared::cluster.b64 [%0];"
                         :: "r"(sb+8) : "memory");
        }
#else
        __syncthreads();
        #pragma unroll
        for (int ks=0;ks<4;ks++){
            uint32_t ahf[4][4], alf[4][4], bhf[4][2], blf[4][2];
            int arow = ((lid>>3)&1)*8 + (lid&7);
            int acol = ks*16 + ((lid>>4)&1)*8;
            #pragma unroll
            for (int mi=0;mi<4;mi++){
                uint32_t off = SWZ((wm0+mi*16+arow)*128 + acol*2);
                ldsm4(ahf[mi], sb+OA_H+off);
                ldsm4(alf[mi], sb+OA_L+off);
            }
            int l2 = lid&15;
            int brow = l2&7;
            int bcol = ks*16 + ((l2>>3)&1)*8;
            #pragma unroll
            for (int ni=0;ni<4;ni++){
                uint32_t off = SWZ((wn0+ni*8+brow)*128 + bcol*2);
                ldsm2(bhf[ni], sb+OB_H+off);
                ldsm2(blf[ni], sb+OB_L+off);
            }
            #pragma unroll
            for (int mi=0;mi<4;mi++)
                #pragma unroll
                for (int ni=0;ni<4;ni++){
                    mma16816(acc[mi][ni], ahf[mi], bhf[ni]);
                    mma16816(acc[mi][ni], ahf[mi], blf[ni]);
                    mma16816(acc[mi][ni], alf[mi], bhf[ni]);
                }
        }
#endif
    }

#if TC_PATH
    mbar_wait(sb+8, 1);
    asm volatile("tcgen05.fence::after_thread_sync;" ::: "memory");
    if (wid<4){
        int m = i0 + wid*32 + lid;
        size_t rowoff = ((size_t)m*BN_ + b)*D1N + h*HDN + d0;
        #pragma unroll
        for (int nb=0;nb<4;nb++){
            uint32_t dr[32];
            tmem_ld32(dr, tb + nb*32);
            asm volatile("tcgen05.wait::ld.sync.aligned;" ::: "memory");
            const float* up = U + rowoff + nb*32;
            uint32_t ph[16], pl[16];
            #pragma unroll
            for (int w=0;w<16;w++){
                float a0 = __uint_as_float(dr[2*w+0]) * up[2*w+0];
                float a1 = __uint_as_float(dr[2*w+1]) * up[2*w+1];
                __nv_bfloat16 h0 = __float2bfloat16(a0), h1 = __float2bfloat16(a1);
                ph[w] = (uint32_t)__bfloat16_as_ushort(h0) | ((uint32_t)__bfloat16_as_ushort(h1)<<16);
                pl[w] = pk(a0-__bfloat162float(h0), a1-__bfloat162float(h1));
            }
            uint4* dh = (uint4*)(Aoh + rowoff + nb*32);
            uint4* dl = (uint4*)(Aol + rowoff + nb*32);
            #pragma unroll
            for (int w=0;w<4;w++){
                dh[w] = make_uint4(ph[4*w],ph[4*w+1],ph[4*w+2],ph[4*w+3]);
                dl[w] = make_uint4(pl[4*w],pl[4*w+1],pl[4*w+2],pl[4*w+3]);
            }
        }
    }
    __syncthreads();
    if (wid==0){
        asm volatile("tcgen05.relinquish_alloc_permit.cta_group::1.sync.aligned;");
        asm volatile("tcgen05.dealloc.cta_group::1.sync.aligned.b32 %0, %1;" :: "r"(tb), "r"(128u));
    }
#else
    #pragma unroll
    for (int mi=0;mi<4;mi++)
        #pragma unroll
        for (int ni=0;ni<4;ni++){
            int d = d0 + wn0 + ni*8 + 2*(lid&3);
            #pragma unroll
            for (int half=0;half<2;half++){
                int m = i0 + wm0 + mi*16 + (lid>>2) + half*8;
                size_t off = ((size_t)m*BN_ + b)*D1N + h*HDN + d;
                float a0 = acc[mi][ni][2*half+0] * U[off];
                float a1 = acc[mi][ni][2*half+1] * U[off+1];
                __nv_bfloat16 h0 = __float2bfloat16(a0), h1 = __float2bfloat16(a1);
                *(uint32_t*)(Aoh + off) =
                    (uint32_t)__bfloat16_as_ushort(h0) | ((uint32_t)__bfloat16_as_ushort(h1)<<16);
                *(uint32_t*)(Aol + off) = pk(a0-__bfloat162float(h0), a1-__bfloat162float(h1));
            }
        }
#endif
}

// ---------------------------------------------------------------------------
extern "C" void kernel_launch(void* const* d_in, const int* in_sizes, int n_in,
                              void* d_out, int out_size)
{
    const float* q   = (const float*)d_in[0];
    const float* u_w = (const float*)d_in[3];
    const float* u_b = (const float*)d_in[4];
    const float* v_w = (const float*)d_in[5];
    const float* v_b = (const float*)d_in[6];
    const float* o_w = (const float*)d_in[7];
    const float* o_b = (const float*)d_in[8];
    const float* pos = (const float*)d_in[9];
    const float* zer = (const float*)d_in[10];
    const float* neg = (const float*)d_in[11];
    float* out = (float*)d_out;

    cudaFuncSetAttribute(gemm_k<0>, cudaFuncAttributeMaxDynamicSharedMemorySize, SMEM_SZ);
    cudaFuncSetAttribute(gemm_k<1>, cudaFuncAttributeMaxDynamicSharedMemorySize, SMEM_SZ);
    cudaFuncSetAttribute(toep_k,    cudaFuncAttributeMaxDynamicSharedMemorySize, SMEM_SZ);

    void *p;
    #define SYM(v, sym) cudaGetSymbolAddress(&p, sym); auto* v = (decltype(&sym[0]))p;
    SYM(xh,  g_xh);  SYM(xl,  g_xl);
    SYM(uwh, g_uwh); SYM(uwl, g_uwl);
    SYM(vwh, g_vwh); SYM(vwl, g_vwl);
    SYM(owh, g_owh); SYM(owl, g_owl);
    SYM(ug,  g_u);   SYM(vg,  g_v);
    SYM(vth, g_vth); SYM(vtl, g_vtl);
    SYM(ah,  g_ah);  SYM(al,  g_al);
    SYM(tth, g_th);  SYM(ttl, g_tl);
    #undef SYM

    rmsnorm_k<<<MN, 256>>>(q, xh, xl);
    split_k<<<(D1N*EN/4+255)/256, 256>>>(u_w, uwh, uwl, D1N*EN/4);
    split_k<<<(D1N*EN/4+255)/256, 256>>>(v_w, vwh, vwl, D1N*EN/4);
    split_k<<<(EN*D1N/4+255)/256, 256>>>(o_w, owh, owl, EN*D1N/4);
    build_t_k<<<dim3(LN/256, HN), 256>>>(pos, zer, neg);
    gemm_k<0><<<dim3(D1N/128, MN/128), 256, SMEM_SZ>>>(xh, xl, uwh, uwl, u_b, nullptr, ug, EN, D1N);
    gemm_k<0><<<dim3(D1N/128, MN/128), 256, SMEM_SZ>>>(xh, xl, vwh, vwl, v_b, nullptr, vg, EN, D1N);
    transsplit_k<<<dim3(LN/32, HDN/32, 32), dim3(32,8)>>>(vg, vth, vtl);
    toep_k<<<dim3(HDN/128, LN/128, 32), 256, SMEM_SZ>>>(vth, vtl, tth, ttl, ug, ah, al);
    gemm_k<1><<<dim3(EN/128, MN/128), 256, SMEM_SZ>>>(ah, al, owh, owl, o_b, q, out, D1N, EN);
}

// round 4
// speedup vs baseline: 2.8720x; 1.4700x over previous
#include <cuda_runtime.h>
#include <cuda_bf16.h>
#include <cstdint>
#include <math.h>

#define LN   2048
#define BN_  4
#define EN   1024
#define HN   8
#define D1N  2048
#define HDN  256
#define MN   (LN*BN_)   // 8192

// ---------------- device scratch ----------------
__device__ __align__(16) __nv_bfloat16 g_xh[MN*EN],  g_xl[MN*EN];
__device__ __align__(16) __nv_bfloat16 g_uwh[D1N*EN], g_uwl[D1N*EN];
__device__ __align__(16) __nv_bfloat16 g_vwh[D1N*EN], g_vwl[D1N*EN];
__device__ __align__(16) __nv_bfloat16 g_owh[EN*D1N], g_owl[EN*D1N];
__device__ __align__(16) float g_u[MN*D1N];
__device__ __align__(16) float g_v[MN*D1N];
__device__ __align__(16) __nv_bfloat16 g_vth[(size_t)32*HDN*LN], g_vtl[(size_t)32*HDN*LN];
__device__ __align__(16) __nv_bfloat16 g_ah[MN*D1N], g_al[MN*D1N];
__device__ __align__(16) __nv_bfloat16 g_th[HN*4096], g_tl[HN*4096];
// precomputed toeplitz A tiles: 8 heads x 62 deltas x (128x64) bf16, pre-swizzled
__device__ __align__(16) __nv_bfloat16 g_tth[(size_t)HN*62*8192], g_ttl[(size_t)HN*62*8192];

// ---------------- helpers ----------------
__device__ __forceinline__ uint32_t smem_u32(const void* p){
    uint32_t a;
    asm("{ .reg .u64 t; cvta.to.shared.u64 t, %1; cvt.u32.u64 %0, t; }" : "=r"(a) : "l"(p));
    return a;
}
#define SWZ(o) ((uint32_t)(o) ^ ((((uint32_t)(o))>>3)&0x70))

__device__ __forceinline__ uint32_t pk(float a, float b){
    __nv_bfloat16 x = __float2bfloat16(a), y = __float2bfloat16(b);
    return (uint32_t)__bfloat16_as_ushort(x) | ((uint32_t)__bfloat16_as_ushort(y)<<16);
}
__device__ __forceinline__ void ldsm4(uint32_t* r, uint32_t addr){
    asm volatile("ldmatrix.sync.aligned.m8n8.x4.shared.b16 {%0,%1,%2,%3}, [%4];"
                 : "=r"(r[0]),"=r"(r[1]),"=r"(r[2]),"=r"(r[3]) : "r"(addr));
}
__device__ __forceinline__ void ldsm2(uint32_t* r, uint32_t addr){
    asm volatile("ldmatrix.sync.aligned.m8n8.x2.shared.b16 {%0,%1}, [%2];"
                 : "=r"(r[0]),"=r"(r[1]) : "r"(addr));
}
__device__ __forceinline__ void mma16816(float* d, const uint32_t* a, const uint32_t* b){
    asm volatile("mma.sync.aligned.m16n8k16.row.col.f32.bf16.bf16.f32 "
        "{%0,%1,%2,%3}, {%4,%5,%6,%7}, {%8,%9}, {%0,%1,%2,%3};"
        : "+f"(d[0]),"+f"(d[1]),"+f"(d[2]),"+f"(d[3])
        : "r"(a[0]),"r"(a[1]),"r"(a[2]),"r"(a[3]), "r"(b[0]),"r"(b[1]));
}
__device__ __forceinline__ void cpa16(uint32_t s, const void* g){
    asm volatile("cp.async.cg.shared.global [%0], [%1], 16;" :: "r"(s), "l"(g));
}
__device__ __forceinline__ void cpa_commit(){ asm volatile("cp.async.commit_group;" ::: "memory"); }
__device__ __forceinline__ void cpa_wait0(){ asm volatile("cp.async.wait_group 0;" ::: "memory"); }

// SMEM: 2 stages x (A_hi 16K | A_lo 16K | B_hi 16K | B_lo 16K)
#define TA_H 0
#define TA_L 16384
#define TB_H 32768
#define TB_L 49152
#define STG  65536
#define SMEM_SZ (2*STG)   // 131072

// ---------------------------------------------------------------------------
__global__ void rmsnorm_k(const float* __restrict__ q,
                          __nv_bfloat16* __restrict__ xh, __nv_bfloat16* __restrict__ xl)
{
    int m = blockIdx.x, t = threadIdx.x;
    float4 a = reinterpret_cast<const float4*>(q + (size_t)m*EN)[t];
    float ss = a.x*a.x + a.y*a.y + a.z*a.z + a.w*a.w;
    #pragma unroll
    for (int o=16;o;o>>=1) ss += __shfl_xor_sync(0xffffffffu, ss, o);
    __shared__ float sred[8];
    if ((t&31)==0) sred[t>>5] = ss;
    __syncthreads();
    if (t<8){
        float v = sred[t];
        #pragma unroll
        for (int o=4;o;o>>=1) v += __shfl_xor_sync(0xffu, v, o);
        if (t==0) sred[0] = v;
    }
    __syncthreads();
    float inv = 1.0f / (sqrtf(sred[0]*(1.0f/EN)) + 1e-8f);
    float v0=a.x*inv, v1=a.y*inv, v2=a.z*inv, v3=a.w*inv;
    __nv_bfloat16 h0=__float2bfloat16(v0), h1=__float2bfloat16(v1),
                  h2=__float2bfloat16(v2), h3=__float2bfloat16(v3);
    size_t off = (size_t)m*EN + t*4;
    uint2 wh = make_uint2(
        (uint32_t)__bfloat16_as_ushort(h0) | ((uint32_t)__bfloat16_as_ushort(h1)<<16),
        (uint32_t)__bfloat16_as_ushort(h2) | ((uint32_t)__bfloat16_as_ushort(h3)<<16));
    uint2 wl = make_uint2(
        pk(v0-__bfloat162float(h0), v1-__bfloat162float(h1)),
        pk(v2-__bfloat162float(h2), v3-__bfloat162float(h3)));
    *reinterpret_cast<uint2*>(xh+off) = wh;
    *reinterpret_cast<uint2*>(xl+off) = wl;
}

__global__ void split_k(const float* __restrict__ w,
                        __nv_bfloat16* __restrict__ oh, __nv_bfloat16* __restrict__ ol, int n4)
{
    int i = blockIdx.x*256 + threadIdx.x;
    if (i >= n4) return;
    float4 a = reinterpret_cast<const float4*>(w)[i];
    __nv_bfloat16 h0=__float2bfloat16(a.x), h1=__float2bfloat16(a.y),
                  h2=__float2bfloat16(a.z), h3=__float2bfloat16(a.w);
    uint2 wh = make_uint2(
        (uint32_t)__bfloat16_as_ushort(h0) | ((uint32_t)__bfloat16_as_ushort(h1)<<16),
        (uint32_t)__bfloat16_as_ushort(h2) | ((uint32_t)__bfloat16_as_ushort(h3)<<16));
    uint2 wl = make_uint2(
        pk(a.x-__bfloat162float(h0), a.y-__bfloat162float(h1)),
        pk(a.z-__bfloat162float(h2), a.w-__bfloat162float(h3)));
    reinterpret_cast<uint2*>(oh)[i] = wh;
    reinterpret_cast<uint2*>(ol)[i] = wl;
}

__global__ void build_t_k(const float* __restrict__ pos, const float* __restrict__ zero,
                          const float* __restrict__ neg)
{
    int h = blockIdx.y;
    int k = blockIdx.x*256 + threadIdx.x;
    if (k >= LN) return;
    int base = h*4096;
    auto wr = [&](int idx, float v){
        __nv_bfloat16 hi = __float2bfloat16(v);
        g_th[base+idx] = hi;
        g_tl[base+idx] = __float2bfloat16(v - __bfloat162float(hi));
    };
    if (k==0){ wr(2047, zero[h]); wr(4095, 0.f); }
    else { wr(2047+k, pos[h*(LN-1)+k-1]); wr(2047-k, neg[h*(LN-1)+k-1]); }
}

// ---------------------------------------------------------------------------
// Precompute toeplitz A tiles: tile[h][ti] (delta=(ti-31)*64) is 128x64 bf16,
// element [m][k] = t[delta + m - k], stored SW128-swizzled (ready for ldmatrix).
// ---------------------------------------------------------------------------
__global__ void toeptiles_k()
{
    __shared__ uint16_t sH[192], sL[192];
    int ti = blockIdx.x, h = blockIdx.y, tid = threadIdx.x;
    int gb = h*4096 + 1984 + (ti-31)*64;   // index of t[delta-63]
    if (tid < 191){
        sH[tid] = ((const uint16_t*)g_th)[gb+tid];
        sL[tid] = ((const uint16_t*)g_tl)[gb+tid];
    }
    __syncthreads();
    size_t tb = ((size_t)h*62 + ti)*8192;   // elements
    char* dh = (char*)g_tth + tb*2;
    char* dl = (char*)g_ttl + tb*2;
    #pragma unroll
    for (int it=0;it<4;it++){
        int idx = it*256+tid, m = idx>>3, k8 = (idx&7)<<3;
        int base = m + 63 - k8;
        uint32_t so = SWZ(m*128 + k8*2);
        uint32_t w0 = (uint32_t)sH[base]   | ((uint32_t)sH[base-1]<<16);
        uint32_t w1 = (uint32_t)sH[base-2] | ((uint32_t)sH[base-3]<<16);
        uint32_t w2 = (uint32_t)sH[base-4] | ((uint32_t)sH[base-5]<<16);
        uint32_t w3 = (uint32_t)sH[base-6] | ((uint32_t)sH[base-7]<<16);
        *(uint4*)(dh+so) = make_uint4(w0,w1,w2,w3);
        w0 = (uint32_t)sL[base]   | ((uint32_t)sL[base-1]<<16);
        w1 = (uint32_t)sL[base-2] | ((uint32_t)sL[base-3]<<16);
        w2 = (uint32_t)sL[base-4] | ((uint32_t)sL[base-5]<<16);
        w3 = (uint32_t)sL[base-6] | ((uint32_t)sL[base-7]<<16);
        *(uint4*)(dl+so) = make_uint4(w0,w1,w2,w3);
    }
}

// ---------------------------------------------------------------------------
// MMA core for a 128x128 tile on one staged buffer (3-segment split).
// ---------------------------------------------------------------------------
struct Acc { float a[4][4][4]; };

__device__ __forceinline__ void mma_stage(Acc& A, uint32_t base, int wm0, int wn0, int lid)
{
    #pragma unroll
    for (int ks=0;ks<4;ks++){
        uint32_t ahf[4][4], alf[4][4], bhf[4][2], blf[4][2];
        int arow = ((lid>>3)&1)*8 + (lid&7);
        int acol = ks*16 + ((lid>>4)&1)*8;
        #pragma unroll
        for (int mi=0;mi<4;mi++){
            uint32_t off = SWZ((wm0+mi*16+arow)*128 + acol*2);
            ldsm4(ahf[mi], base+TA_H+off);
            ldsm4(alf[mi], base+TA_L+off);
        }
        int l2 = lid&15;
        int brow = l2&7;
        int bcol = ks*16 + ((l2>>3)&1)*8;
        #pragma unroll
        for (int ni=0;ni<4;ni++){
            uint32_t off = SWZ((wn0+ni*8+brow)*128 + bcol*2);
            ldsm2(bhf[ni], base+TB_H+off);
            ldsm2(blf[ni], base+TB_L+off);
        }
        #pragma unroll
        for (int mi=0;mi<4;mi++)
            #pragma unroll
            for (int ni=0;ni<4;ni++){
                mma16816(A.a[mi][ni], ahf[mi], bhf[ni]);
                mma16816(A.a[mi][ni], ahf[mi], blf[ni]);
                mma16816(A.a[mi][ni], alf[mi], bhf[ni]);
            }
    }
}

// ---------------------------------------------------------------------------
// Pipelined split-bf16 GEMM, tile 128x128, K-chunk 64, 2-stage cp.async.
// EPI 0: silu(acc+bias) -> f32. EPI 1: acc+bias+resid -> f32.
// ---------------------------------------------------------------------------
template<int EPI>
__global__ void __launch_bounds__(256)
gemm_k(const __nv_bfloat16* __restrict__ Ah, const __nv_bfloat16* __restrict__ Al,
       const __nv_bfloat16* __restrict__ Bh, const __nv_bfloat16* __restrict__ Bl,
       const float* __restrict__ bias, const float* __restrict__ resid,
       float* __restrict__ C, int K, int Nld)
{
    extern __shared__ char smem[];
    const uint32_t sb = smem_u32(smem);
    int tid = threadIdx.x, wid = tid>>5, lid = tid&31;
    int i0 = blockIdx.y*128, n0 = blockIdx.x*128;
    int wm0 = (wid>>2)*64, wn0 = (wid&3)*32;
    Acc acc;
    #pragma unroll
    for (int i=0;i<4;i++)
        #pragma unroll
        for (int j=0;j<4;j++)
            #pragma unroll
            for (int r=0;r<4;r++) acc.a[i][j][r] = 0.f;

    int lr = tid>>3, lq = tid&7;                 // 256 thr -> 32 rows x 8 chunks per pass
    uint32_t soT = SWZ(lr*128 + lq*16);

    auto load_chunk = [&](int c, int st){
        uint32_t bs = sb + st*STG;
        int kt = c<<6;
        #pragma unroll
        for (int it=0;it<4;it++){
            int r = lr + it*32;
            uint32_t so = soT + it*(32*128);
            size_t goA = (size_t)(i0+r)*K + kt + lq*8;
            size_t goB = (size_t)(n0+r)*K + kt + lq*8;
            cpa16(bs+TA_H+so, Ah+goA);
            cpa16(bs+TA_L+so, Al+goA);
            cpa16(bs+TB_H+so, Bh+goB);
            cpa16(bs+TB_L+so, Bl+goB);
        }
        cpa_commit();
    };

    const int nch = K>>6;
    load_chunk(0, 0);
    for (int c=0;c<nch;c++){
        cpa_wait0();
        __syncthreads();
        if (c+1 < nch) load_chunk(c+1, (c+1)&1);
        mma_stage(acc, sb + (c&1)*STG, wm0, wn0, lid);
        __syncthreads();
    }

    #pragma unroll
    for (int mi=0;mi<4;mi++)
        #pragma unroll
        for (int ni=0;ni<4;ni++){
            int nn = n0 + wn0 + ni*8 + 2*(lid&3);
            #pragma unroll
            for (int half=0;half<2;half++){
                int m = i0 + wm0 + mi*16 + (lid>>2) + half*8;
                float v0 = acc.a[mi][ni][2*half+0], v1 = acc.a[mi][ni][2*half+1];
                float o0, o1;
                if (EPI==0){
                    float s0 = v0 + bias[nn], s1 = v1 + bias[nn+1];
                    o0 = s0 / (1.0f + __expf(-s0)); o1 = s1 / (1.0f + __expf(-s1));
                } else {
                    const float* rp = resid + (size_t)m*Nld + nn;
                    o0 = v0 + bias[nn] + rp[0]; o1 = v1 + bias[nn+1] + rp[1];
                }
                *(float2*)(C + (size_t)m*Nld + nn) = make_float2(o0, o1);
            }
        }
}

// ---------------------------------------------------------------------------
// transpose + split v
// ---------------------------------------------------------------------------
__global__ void transsplit_k(const float* __restrict__ V,
                             __nv_bfloat16* __restrict__ Oh, __nv_bfloat16* __restrict__ Ol)
{
    __shared__ float t[32][33];
    int s = blockIdx.z, h = s>>2, b = s&3;
    int j0 = blockIdx.x*32, d0 = blockIdx.y*32;
    int tx = threadIdx.x, ty = threadIdx.y;
    #pragma unroll
    for (int r=0;r<4;r++){
        int j = j0 + ty + r*8;
        t[ty+r*8][tx] = V[((size_t)j*BN_ + b)*D1N + h*HDN + d0 + tx];
    }
    __syncthreads();
    #pragma unroll
    for (int r=0;r<4;r++){
        int d = d0 + ty + r*8;
        float v = t[tx][ty+r*8];
        __nv_bfloat16 hi = __float2bfloat16(v);
        size_t off = ((size_t)s*HDN + d)*LN + j0 + tx;
        Oh[off] = hi;
        Ol[off] = __float2bfloat16(v - __bfloat162float(hi));
    }
}

// ---------------------------------------------------------------------------
// Pipelined toeplitz GEMM: A from precomputed tiles, B from vth/vtl.
// Tile 128 (l) x 128 (d), K-chunk 64 over j, 32 chunks. Fused gating epilogue.
// ---------------------------------------------------------------------------
__global__ void __launch_bounds__(256)
toep_k(const __nv_bfloat16* __restrict__ Vh_, const __nv_bfloat16* __restrict__ Vl_,
       const float* __restrict__ U,
       __nv_bfloat16* __restrict__ Aoh, __nv_bfloat16* __restrict__ Aol)
{
    extern __shared__ char smem[];
    const uint32_t sb = smem_u32(smem);
    int tid = threadIdx.x, wid = tid>>5, lid = tid&31;
    int s = blockIdx.z, h = s>>2, b = s&3;
    int i0 = blockIdx.y*128;
    int d0 = blockIdx.x*128;
    int wm0 = (wid>>2)*64, wn0 = (wid&3)*32;
    const __nv_bfloat16* vh = Vh_ + (size_t)s*HDN*LN + (size_t)d0*LN;
    const __nv_bfloat16* vl = Vl_ + (size_t)s*HDN*LN + (size_t)d0*LN;
    Acc acc;
    #pragma unroll
    for (int i=0;i<4;i++)
        #pragma unroll
        for (int j=0;j<4;j++)
            #pragma unroll
            for (int r=0;r<4;r++) acc.a[i][j][r] = 0.f;

    int lr = tid>>3, lq = tid&7;
    uint32_t soT = SWZ(lr*128 + lq*16);
    int tibase = (blockIdx.y<<1) + 31;        // ti = 2*by + 31 - c

    auto load_chunk = [&](int c, int st){
        uint32_t bs = sb + st*STG;
        int j0 = c<<6;
        size_t tb = ((size_t)h*62 + (tibase - c))*8192;   // elements
        const char* th = (const char*)g_tth + tb*2;
        const char* tl = (const char*)g_ttl + tb*2;
        #pragma unroll
        for (int it=0;it<4;it++){
            int r = lr + it*32;
            uint32_t lin = (uint32_t)(it*256+tid)*16;     // linear 16B index into tile
            cpa16(bs+TA_H+lin, th+lin);
            cpa16(bs+TA_L+lin, tl+lin);
            uint32_t so = soT + it*(32*128);
            size_t go = (size_t)r*LN + j0 + lq*8;
            cpa16(bs+TB_H+so, vh+go);
            cpa16(bs+TB_L+so, vl+go);
        }
        cpa_commit();
    };

    load_chunk(0, 0);
    for (int c=0;c<32;c++){
        cpa_wait0();
        __syncthreads();
        if (c+1 < 32) load_chunk(c+1, (c+1)&1);
        mma_stage(acc, sb + (c&1)*STG, wm0, wn0, lid);
        __syncthreads();
    }

    #pragma unroll
    for (int mi=0;mi<4;mi++)
        #pragma unroll
        for (int ni=0;ni<4;ni++){
            int d = d0 + wn0 + ni*8 + 2*(lid&3);
            #pragma unroll
            for (int half=0;half<2;half++){
                int m = i0 + wm0 + mi*16 + (lid>>2) + half*8;
                size_t off = ((size_t)m*BN_ + b)*D1N + h*HDN + d;
                float a0 = acc.a[mi][ni][2*half+0] * U[off];
                float a1 = acc.a[mi][ni][2*half+1] * U[off+1];
                __nv_bfloat16 h0 = __float2bfloat16(a0), h1 = __float2bfloat16(a1);
                *(uint32_t*)(Aoh + off) =
                    (uint32_t)__bfloat16_as_ushort(h0) | ((uint32_t)__bfloat16_as_ushort(h1)<<16);
                *(uint32_t*)(Aol + off) = pk(a0-__bfloat162float(h0), a1-__bfloat162float(h1));
            }
        }
}

// ---------------------------------------------------------------------------
extern "C" void kernel_launch(void* const* d_in, const int* in_sizes, int n_in,
                              void* d_out, int out_size)
{
    const float* q   = (const float*)d_in[0];
    const float* u_w = (const float*)d_in[3];
    const float* u_b = (const float*)d_in[4];
    const float* v_w = (const float*)d_in[5];
    const float* v_b = (const float*)d_in[6];
    const float* o_w = (const float*)d_in[7];
    const float* o_b = (const float*)d_in[8];
    const float* pos = (const float*)d_in[9];
    const float* zer = (const float*)d_in[10];
    const float* neg = (const float*)d_in[11];
    float* out = (float*)d_out;

    cudaFuncSetAttribute(gemm_k<0>, cudaFuncAttributeMaxDynamicSharedMemorySize, SMEM_SZ);
    cudaFuncSetAttribute(gemm_k<1>, cudaFuncAttributeMaxDynamicSharedMemorySize, SMEM_SZ);
    cudaFuncSetAttribute(toep_k,    cudaFuncAttributeMaxDynamicSharedMemorySize, SMEM_SZ);

    void *p;
    #define SYM(v, sym) cudaGetSymbolAddress(&p, sym); auto* v = (decltype(&sym[0]))p;
    SYM(xh,  g_xh);  SYM(xl,  g_xl);
    SYM(uwh, g_uwh); SYM(uwl, g_uwl);
    SYM(vwh, g_vwh); SYM(vwl, g_vwl);
    SYM(owh, g_owh); SYM(owl, g_owl);
    SYM(ug,  g_u);   SYM(vg,  g_v);
    SYM(vth, g_vth); SYM(vtl, g_vtl);
    SYM(ah,  g_ah);  SYM(al,  g_al);
    #undef SYM

    rmsnorm_k<<<MN, 256>>>(q, xh, xl);
    split_k<<<(D1N*EN/4+255)/256, 256>>>(u_w, uwh, uwl, D1N*EN/4);
    split_k<<<(D1N*EN/4+255)/256, 256>>>(v_w, vwh, vwl, D1N*EN/4);
    split_k<<<(EN*D1N/4+255)/256, 256>>>(o_w, owh, owl, EN*D1N/4);
    build_t_k<<<dim3(LN/256, HN), 256>>>(pos, zer, neg);
    toeptiles_k<<<dim3(62, HN), 256>>>();
    gemm_k<0><<<dim3(D1N/128, MN/128), 256, SMEM_SZ>>>(xh, xl, uwh, uwl, u_b, nullptr, ug, EN, D1N);
    gemm_k<0><<<dim3(D1N/128, MN/128), 256, SMEM_SZ>>>(xh, xl, vwh, vwl, v_b, nullptr, vg, EN, D1N);
    transsplit_k<<<dim3(LN/32, HDN/32, 32), dim3(32,8)>>>(vg, vth, vtl);
    toep_k<<<dim3(HDN/128, LN/128, 32), 256, SMEM_SZ>>>(vth, vtl, ug, ah, al);
    gemm_k<1><<<dim3(EN/128, MN/128), 256, SMEM_SZ>>>(ah, al, owh, owl, o_b, q, out, D1N, EN);
}